// round 3
// baseline (speedup 1.0000x reference)
#include <cuda_runtime.h>

#define NN 1395
#define EE 44640

// ---------------- scratch (device globals; no allocation allowed) ----------
__device__ __align__(16) float g_xw[NN * 3];
__device__ __align__(16) float g_acc[NN * 3];
__device__ __align__(16) float g_h[NN * 3];
__device__ int   g_deg[NN];
__device__ float g_dinv[NN];
__device__ __align__(16) float g_v1[2048];
__device__ __align__(16) float g_v2[4096];
__device__ __align__(16) float g_c1[32 * 58 * 58];
__device__ __align__(16) float g_c2[32 * 54 * 54];
__device__ __align__(16) float g_c3[64 * 52 * 52];
__device__ __align__(16) float g_c4[64 * 50 * 50];
__device__ __align__(16) float g_f3[2048];
__device__ __align__(16) float g_f4[2048];
__device__ int g_idx64;   // 1 if edge_index is int64 in memory, 0 if int32

// ---------------- edge-index dtype detection --------------------------------
// Buffer holds 2*EE logical values. If int64: first 89280 dwords are
// (lo,hi,lo,hi,...) with hi == 0 for all values < 2^31. If int32: those
// dwords are real node indices (0..1394), some odd-position ones nonzero.
// Reading only the first 2*EE dwords is safe under either layout.
__global__ void k_detect(const unsigned int* __restrict__ ei) {
    __shared__ int nz;
    if (threadIdx.x == 0) nz = 0;
    __syncthreads();
    for (int i = threadIdx.x; i < EE; i += blockDim.x) {
        if (ei[2 * i + 1] != 0u) nz = 1;
    }
    __syncthreads();
    if (threadIdx.x == 0) g_idx64 = (nz == 0) ? 1 : 0;
}

__device__ __forceinline__ int load_idx(const void* ei, int pos) {
    if (g_idx64) return (int)((const long long*)ei)[pos];
    return ((const int*)ei)[pos];
}

// ---------------- GCN kernels ----------------------------------------------
__global__ void k_deg_zero() {
    int i = blockIdx.x * blockDim.x + threadIdx.x;
    if (i < NN) g_deg[i] = 0;
}

__global__ void k_deg_count(const void* __restrict__ ei) {
    int e = blockIdx.x * blockDim.x + threadIdx.x;
    if (e < EE) {
        int d = load_idx(ei, EE + e);
        if (d >= 0 && d < NN) atomicAdd(&g_deg[d], 1);
    }
}

__global__ void k_dinv() {
    int i = blockIdx.x * blockDim.x + threadIdx.x;
    if (i < NN) g_dinv[i] = rsqrtf((float)(g_deg[i] + 1));  // +1 self loop
}

// xw = x_masked @ W1 : x[:, :3] zeroed, so only cols 3..5 contribute
__global__ void k_xw1(const float* __restrict__ x, const float* __restrict__ W1) {
    int i = blockIdx.x * blockDim.x + threadIdx.x;
    if (i >= NN) return;
    float x3 = x[i * 6 + 3], x4 = x[i * 6 + 4], x5 = x[i * 6 + 5];
#pragma unroll
    for (int c = 0; c < 3; c++)
        g_xw[i * 3 + c] = x3 * W1[3 * 3 + c] + x4 * W1[4 * 3 + c] + x5 * W1[5 * 3 + c];
}

// xw = h @ W2  (3x3)
__global__ void k_xw2(const float* __restrict__ W2) {
    int i = blockIdx.x * blockDim.x + threadIdx.x;
    if (i >= NN) return;
    float h0 = g_h[i * 3 + 0], h1 = g_h[i * 3 + 1], h2 = g_h[i * 3 + 2];
#pragma unroll
    for (int c = 0; c < 3; c++)
        g_xw[i * 3 + c] = h0 * W2[0 * 3 + c] + h1 * W2[1 * 3 + c] + h2 * W2[2 * 3 + c];
}

// acc[i] = dinv[i]^2 * xw[i]  (self-loop term)
__global__ void k_self() {
    int i = blockIdx.x * blockDim.x + threadIdx.x;
    if (i >= NN) return;
    float d2 = g_dinv[i] * g_dinv[i];
#pragma unroll
    for (int c = 0; c < 3; c++) g_acc[i * 3 + c] = d2 * g_xw[i * 3 + c];
}

// per-edge scatter: acc[dst] += dinv[src]*dinv[dst] * xw[src]
__global__ void k_scatter(const void* __restrict__ ei) {
    int e = blockIdx.x * blockDim.x + threadIdx.x;
    if (e >= EE) return;
    int s = load_idx(ei, e);
    int d = load_idx(ei, EE + e);
    if (s < 0 || s >= NN || d < 0 || d >= NN) return;
    float n = g_dinv[s] * g_dinv[d];
    atomicAdd(&g_acc[d * 3 + 0], n * g_xw[s * 3 + 0]);
    atomicAdd(&g_acc[d * 3 + 1], n * g_xw[s * 3 + 1]);
    atomicAdd(&g_acc[d * 3 + 2], n * g_xw[s * 3 + 2]);
}

// h = leaky_relu(acc + b)
__global__ void k_final(const float* __restrict__ b) {
    int i = blockIdx.x * blockDim.x + threadIdx.x;
    if (i >= NN) return;
#pragma unroll
    for (int c = 0; c < 3; c++) {
        float v = g_acc[i * 3 + c] + b[c];
        g_h[i * 3 + c] = (v >= 0.f) ? v : 0.2f * v;
    }
}

// ---------------- matvec device impls --------------------------------------
__device__ __forceinline__ void matvec_s_impl(const float* __restrict__ W,
                                              const float* __restrict__ x,
                                              const float* __restrict__ b,
                                              float* __restrict__ out, int cols) {
    int r = blockIdx.x;
    const float* wr = W + (size_t)r * cols;
    float a = 0.f;
    for (int i = threadIdx.x; i < cols; i += blockDim.x) a += wr[i] * x[i];
    __shared__ float s[256];
    s[threadIdx.x] = a;
    __syncthreads();
    for (int st = 128; st > 0; st >>= 1) {
        if (threadIdx.x < st) s[threadIdx.x] += s[threadIdx.x + st];
        __syncthreads();
    }
    if (threadIdx.x == 0) out[r] = s[0] + b[r];
}

__device__ __forceinline__ void matvec_v4_impl(const float* __restrict__ W,
                                               const float* __restrict__ x,
                                               const float* __restrict__ b,
                                               float* __restrict__ out, int cols) {
    int r = blockIdx.x;
    int nc4 = cols >> 2;
    const float4* w4 = (const float4*)(W + (size_t)r * cols);
    const float4* x4 = (const float4*)x;
    float a = 0.f;
    for (int i = threadIdx.x; i < nc4; i += blockDim.x) {
        float4 w = w4[i];
        float4 xv = x4[i];
        a += w.x * xv.x + w.y * xv.y + w.z * xv.z + w.w * xv.w;
    }
    __shared__ float s[256];
    s[threadIdx.x] = a;
    __syncthreads();
    for (int st = 128; st > 0; st >>= 1) {
        if (threadIdx.x < st) s[threadIdx.x] += s[threadIdx.x + st];
        __syncthreads();
    }
    if (threadIdx.x == 0) out[r] = s[0] + b[r];
}

// wrapper kernels (globals referenced on device side only)
__global__ void k_fc1(const float* __restrict__ W, const float* __restrict__ b) {
    matvec_s_impl(W, g_h, b, g_v1, 4185);
}
__global__ void k_fc2(const float* __restrict__ W, const float* __restrict__ b) {
    matvec_v4_impl(W, g_v1, b, g_v2, 2048);
}
__global__ void k_fc4(const float* __restrict__ W, const float* __restrict__ b) {
    matvec_v4_impl(W, g_f3, b, g_f4, 2048);
}
__global__ void k_fc5(const float* __restrict__ W, const float* __restrict__ b,
                      float* __restrict__ out) {
    matvec_v4_impl(W, g_f4, b, out, 2048);
}

// fc3: 2048 x 160000 — 4 rows per block to amortize x reads from L2.
__global__ void k_fc3(const float* __restrict__ W, const float* __restrict__ b) {
    const int NC4 = 160000 / 4;  // 40000
    int r0 = blockIdx.x * 4;
    const float4* x4 = (const float4*)g_c4;
    const float4* w4 = (const float4*)W + (size_t)r0 * NC4;
    float a0 = 0.f, a1 = 0.f, a2 = 0.f, a3 = 0.f;
    for (int i = threadIdx.x; i < NC4; i += blockDim.x) {
        float4 xv = x4[i];
        float4 w;
        w = w4[i];            a0 += w.x * xv.x + w.y * xv.y + w.z * xv.z + w.w * xv.w;
        w = w4[i + NC4];      a1 += w.x * xv.x + w.y * xv.y + w.z * xv.z + w.w * xv.w;
        w = w4[i + 2 * NC4];  a2 += w.x * xv.x + w.y * xv.y + w.z * xv.z + w.w * xv.w;
        w = w4[i + 3 * NC4];  a3 += w.x * xv.x + w.y * xv.y + w.z * xv.z + w.w * xv.w;
    }
    __shared__ float4 s[256];
    s[threadIdx.x] = make_float4(a0, a1, a2, a3);
    __syncthreads();
    for (int st = 128; st > 0; st >>= 1) {
        if (threadIdx.x < st) {
            s[threadIdx.x].x += s[threadIdx.x + st].x;
            s[threadIdx.x].y += s[threadIdx.x + st].y;
            s[threadIdx.x].z += s[threadIdx.x + st].z;
            s[threadIdx.x].w += s[threadIdx.x + st].w;
        }
        __syncthreads();
    }
    if (threadIdx.x == 0) {
        float4 r = s[0];
        g_f3[r0 + 0] = r.x + b[r0 + 0];
        g_f3[r0 + 1] = r.y + b[r0 + 1];
        g_f3[r0 + 2] = r.z + b[r0 + 2];
        g_f3[r0 + 3] = r.w + b[r0 + 3];
    }
}

// ---------------- conv device impl -----------------------------------------
// Direct conv, valid padding, stride 1. grid = (CO, tiles), 256 threads.
// Weights for the block's output channel live in shared; input via L1/L2.
template <int CI, int KH, int KW>
__device__ __forceinline__ void conv_impl(const float* __restrict__ in,
                                          const float* __restrict__ w,
                                          const float* __restrict__ b,
                                          float* __restrict__ out,
                                          int H, int W, int OH, int OW) {
    __shared__ float sw[CI * KH * KW];
    int oc = blockIdx.x;
    for (int i = threadIdx.x; i < CI * KH * KW; i += blockDim.x)
        sw[i] = w[oc * CI * KH * KW + i];
    __syncthreads();

    int p = blockIdx.y * blockDim.x + threadIdx.x;
    if (p >= OH * OW) return;
    int oy = p / OW, ox = p % OW;
    float acc = b[oc];
#pragma unroll 2
    for (int ic = 0; ic < CI; ic++) {
        const float* ip = in + ((size_t)ic * H + oy) * W + ox;
        const float* wp = sw + ic * KH * KW;
#pragma unroll
        for (int i = 0; i < KH; i++) {
#pragma unroll
            for (int j = 0; j < KW; j++)
                acc += wp[i * KW + j] * ip[i * W + j];
        }
    }
    out[((size_t)oc * OH + oy) * OW + ox] = acc;
}

__global__ void k_conv1(const float* __restrict__ w, const float* __restrict__ b) {
    conv_impl<1, 7, 7>(g_v2, w, b, g_c1, 64, 64, 58, 58);
}
__global__ void k_conv2(const float* __restrict__ w, const float* __restrict__ b) {
    conv_impl<32, 5, 5>(g_c1, w, b, g_c2, 58, 58, 54, 54);
}
__global__ void k_conv3(const float* __restrict__ w, const float* __restrict__ b) {
    conv_impl<32, 3, 3>(g_c2, w, b, g_c3, 54, 54, 52, 52);
}
__global__ void k_conv4(const float* __restrict__ w, const float* __restrict__ b) {
    conv_impl<64, 3, 3>(g_c3, w, b, g_c4, 52, 52, 50, 50);
}

// ---------------- launcher --------------------------------------------------
extern "C" void kernel_launch(void* const* d_in, const int* in_sizes, int n_in,
                              void* d_out, int out_size) {
    const float* x     = (const float*)d_in[0];
    const void*  ei    = d_in[1];
    const float* W1    = (const float*)d_in[2];
    const float* b1    = (const float*)d_in[3];
    const float* W2    = (const float*)d_in[4];
    const float* b2    = (const float*)d_in[5];
    const float* fc1_w = (const float*)d_in[6];
    const float* fc1_b = (const float*)d_in[7];
    const float* fc2_w = (const float*)d_in[8];
    const float* fc2_b = (const float*)d_in[9];
    const float* c1_w  = (const float*)d_in[10];
    const float* c1_b  = (const float*)d_in[11];
    const float* c2_w  = (const float*)d_in[12];
    const float* c2_b  = (const float*)d_in[13];
    const float* c3_w  = (const float*)d_in[14];
    const float* c3_b  = (const float*)d_in[15];
    const float* c4_w  = (const float*)d_in[16];
    const float* c4_b  = (const float*)d_in[17];
    const float* fc3_w = (const float*)d_in[18];
    const float* fc3_b = (const float*)d_in[19];
    const float* fc4_w = (const float*)d_in[20];
    const float* fc4_b = (const float*)d_in[21];
    const float* fc5_w = (const float*)d_in[22];
    const float* fc5_b = (const float*)d_in[23];
    float* out = (float*)d_out;

    const int TB = 256;
    const int NB_N = (NN + TB - 1) / TB;   // node-grain grids
    const int NB_E = (EE + TB - 1) / TB;   // edge-grain grids

    // ---- edge index dtype detection (int32 vs int64 in device memory)
    k_detect<<<1, 1024>>>((const unsigned int*)ei);

    // ---- degrees / normalization (shared by both GCN layers)
    k_deg_zero<<<NB_N, TB>>>();
    k_deg_count<<<NB_E, TB>>>(ei);
    k_dinv<<<NB_N, TB>>>();

    // ---- GCN layer 1
    k_xw1<<<NB_N, TB>>>(x, W1);
    k_self<<<NB_N, TB>>>();
    k_scatter<<<NB_E, TB>>>(ei);
    k_final<<<NB_N, TB>>>(b1);

    // ---- GCN layer 2
    k_xw2<<<NB_N, TB>>>(W2);
    k_self<<<NB_N, TB>>>();
    k_scatter<<<NB_E, TB>>>(ei);
    k_final<<<NB_N, TB>>>(b2);

    // ---- fc1: [2048,4185] ; fc2: [4096,2048]
    k_fc1<<<2048, TB>>>(fc1_w, fc1_b);
    k_fc2<<<4096, TB>>>(fc2_w, fc2_b);

    // ---- conv chain
    {
        dim3 g1(32, (58 * 58 + TB - 1) / TB);
        k_conv1<<<g1, TB>>>(c1_w, c1_b);
        dim3 g2(32, (54 * 54 + TB - 1) / TB);
        k_conv2<<<g2, TB>>>(c2_w, c2_b);
        dim3 g3(64, (52 * 52 + TB - 1) / TB);
        k_conv3<<<g3, TB>>>(c3_w, c3_b);
        dim3 g4(64, (50 * 50 + TB - 1) / TB);
        k_conv4<<<g4, TB>>>(c4_w, c4_b);
    }

    // ---- fc3: [2048,160000] — the DRAM-bound monster (1.31 GB weight read)
    k_fc3<<<2048 / 4, TB>>>(fc3_w, fc3_b);
    // ---- fc4: [2048,2048]
    k_fc4<<<2048, TB>>>(fc4_w, fc4_b);
    // ---- fc5: [48,2048] -> output
    k_fc5<<<48, TB>>>(fc5_w, fc5_b, out);
}

// round 4
// speedup vs baseline: 1.0362x; 1.0362x over previous
#include <cuda_runtime.h>

#define NN 1395
#define EE 44640

// ---------------- scratch (device globals; no allocation allowed) ----------
__device__ __align__(16) float g_xw[NN * 3];
__device__ __align__(16) float g_acc[NN * 3];
__device__ __align__(16) float g_h[NN * 3];
__device__ int   g_deg[NN];
__device__ float g_dinv[NN];
__device__ __align__(16) float g_v1[2048];
__device__ __align__(16) float g_v2[4096];
__device__ __align__(16) float g_c1[32 * 58 * 58];
__device__ __align__(16) float g_c2[32 * 54 * 54];
__device__ __align__(16) float g_c3[64 * 52 * 52];
__device__ __align__(16) float g_c4[64 * 50 * 50];
__device__ __align__(16) float g_f3[2048];
__device__ __align__(16) float g_f4[2048];
__device__ int g_idx64;   // 1 if edge_index is int64 in memory, 0 if int32

// ---------------- edge-index dtype detection --------------------------------
__global__ void k_detect(const unsigned int* __restrict__ ei) {
    __shared__ int nz;
    if (threadIdx.x == 0) nz = 0;
    __syncthreads();
    for (int i = threadIdx.x; i < EE; i += blockDim.x) {
        if (ei[2 * i + 1] != 0u) nz = 1;
    }
    __syncthreads();
    if (threadIdx.x == 0) g_idx64 = (nz == 0) ? 1 : 0;
}

__device__ __forceinline__ int load_idx(const void* ei, int pos) {
    if (g_idx64) return (int)((const long long*)ei)[pos];
    return ((const int*)ei)[pos];
}

// ---------------- init: zero deg + seed f3 with bias ------------------------
__global__ void k_init(const float* __restrict__ fc3_b) {
    int i = blockIdx.x * blockDim.x + threadIdx.x;
    if (i < NN) g_deg[i] = 0;
    if (i < 2048) g_f3[i] = fc3_b[i];
}

__global__ void k_deg_count(const void* __restrict__ ei) {
    int e = blockIdx.x * blockDim.x + threadIdx.x;
    if (e < EE) {
        int d = load_idx(ei, EE + e);
        if (d >= 0 && d < NN) atomicAdd(&g_deg[d], 1);
    }
}

// dinv + xw1 + self-loop term, fused (node-grain)
__global__ void k_node1(const float* __restrict__ x, const float* __restrict__ W1) {
    int i = blockIdx.x * blockDim.x + threadIdx.x;
    if (i >= NN) return;
    float di = rsqrtf((float)(g_deg[i] + 1));
    g_dinv[i] = di;
    float x3 = x[i * 6 + 3], x4 = x[i * 6 + 4], x5 = x[i * 6 + 5];
    float d2 = di * di;
#pragma unroll
    for (int c = 0; c < 3; c++) {
        float xw = x3 * W1[3 * 3 + c] + x4 * W1[4 * 3 + c] + x5 * W1[5 * 3 + c];
        g_xw[i * 3 + c] = xw;
        g_acc[i * 3 + c] = d2 * xw;
    }
}

// per-edge scatter: acc[dst] += dinv[src]*dinv[dst] * xw[src]
__global__ void k_scatter(const void* __restrict__ ei) {
    int e = blockIdx.x * blockDim.x + threadIdx.x;
    if (e >= EE) return;
    int s = load_idx(ei, e);
    int d = load_idx(ei, EE + e);
    if (s < 0 || s >= NN || d < 0 || d >= NN) return;
    float n = g_dinv[s] * g_dinv[d];
    atomicAdd(&g_acc[d * 3 + 0], n * g_xw[s * 3 + 0]);
    atomicAdd(&g_acc[d * 3 + 1], n * g_xw[s * 3 + 1]);
    atomicAdd(&g_acc[d * 3 + 2], n * g_xw[s * 3 + 2]);
}

// final(layer1) + xw2 + self2, fused (node-grain)
__global__ void k_node2(const float* __restrict__ b1, const float* __restrict__ W2) {
    int i = blockIdx.x * blockDim.x + threadIdx.x;
    if (i >= NN) return;
    float h[3];
#pragma unroll
    for (int c = 0; c < 3; c++) {
        float v = g_acc[i * 3 + c] + b1[c];
        h[c] = (v >= 0.f) ? v : 0.2f * v;
    }
    float di = g_dinv[i];
    float d2 = di * di;
#pragma unroll
    for (int c = 0; c < 3; c++) {
        float xw = h[0] * W2[0 * 3 + c] + h[1] * W2[1 * 3 + c] + h[2] * W2[2 * 3 + c];
        g_xw[i * 3 + c] = xw;
        g_acc[i * 3 + c] = d2 * xw;
    }
}

// h = leaky_relu(acc + b2)
__global__ void k_final2(const float* __restrict__ b) {
    int i = blockIdx.x * blockDim.x + threadIdx.x;
    if (i >= NN) return;
#pragma unroll
    for (int c = 0; c < 3; c++) {
        float v = g_acc[i * 3 + c] + b[c];
        g_h[i * 3 + c] = (v >= 0.f) ? v : 0.2f * v;
    }
}

// ---------------- warp-per-row matvec helpers -------------------------------
__device__ __forceinline__ float warp_red(float a) {
#pragma unroll
    for (int o = 16; o > 0; o >>= 1)
        a += __shfl_down_sync(0xFFFFFFFFu, a, o);
    return a;
}

// scalar cols (fc1: 4185)
__device__ __forceinline__ void matvec_warp_s(const float* __restrict__ W,
                                              const float* __restrict__ x,
                                              const float* __restrict__ b,
                                              float* __restrict__ out,
                                              int rows, int cols) {
    int warp = (blockIdx.x * blockDim.x + threadIdx.x) >> 5;
    int lane = threadIdx.x & 31;
    if (warp >= rows) return;
    const float* wr = W + (size_t)warp * cols;
    float a = 0.f;
    for (int i = lane; i < cols; i += 32) a += __ldcs(&wr[i]) * x[i];
    a = warp_red(a);
    if (lane == 0) out[warp] = a + b[warp];
}

// float4 cols
__device__ __forceinline__ void matvec_warp_v4(const float* __restrict__ W,
                                               const float* __restrict__ x,
                                               const float* __restrict__ b,
                                               float* __restrict__ out,
                                               int rows, int cols) {
    int warp = (blockIdx.x * blockDim.x + threadIdx.x) >> 5;
    int lane = threadIdx.x & 31;
    if (warp >= rows) return;
    int nc4 = cols >> 2;
    const float4* w4 = (const float4*)(W + (size_t)warp * cols);
    const float4* x4 = (const float4*)x;
    float a = 0.f;
    for (int i = lane; i < nc4; i += 32) {
        float4 w = __ldcs(&w4[i]);
        float4 xv = x4[i];
        a += w.x * xv.x + w.y * xv.y + w.z * xv.z + w.w * xv.w;
    }
    a = warp_red(a);
    if (lane == 0) out[warp] = a + b[warp];
}

__global__ void k_fc1(const float* __restrict__ W, const float* __restrict__ b) {
    matvec_warp_s(W, g_h, b, g_v1, 2048, 4185);
}
__global__ void k_fc2(const float* __restrict__ W, const float* __restrict__ b) {
    matvec_warp_v4(W, g_v1, b, g_v2, 4096, 2048);
}
__global__ void k_fc4(const float* __restrict__ W, const float* __restrict__ b) {
    matvec_warp_v4(W, g_f3, b, g_f4, 2048, 2048);
}
__global__ void k_fc5(const float* __restrict__ W, const float* __restrict__ b,
                      float* __restrict__ out) {
    matvec_warp_v4(W, g_f4, b, out, 48, 2048);
}

// ---------------- fc3: 2048x160000, persistent chunked ----------------------
// 4096 chunks = 512 row-groups(4 rows) x 8 column-splits (5000 float4 each).
// Grid 592 = 4 blocks/SM exactly; grid-stride; atomicAdd into bias-seeded g_f3.
__global__ void k_fc3(const float* __restrict__ W) {
    const int NC4 = 40000;     // float4 per row
    const int CHUNK = 5000;    // float4 per row per column-split
    const int NCHUNK = 512 * 8;
    __shared__ float4 s[256];
    for (int c = blockIdx.x; c < NCHUNK; c += gridDim.x) {
        int rg = c >> 3;
        int cs = c & 7;
        int r0 = rg * 4;
        const float4* x4 = (const float4*)g_c4 + cs * CHUNK;
        const float4* w4 = (const float4*)W + (size_t)r0 * NC4 + cs * CHUNK;
        float a0 = 0.f, a1 = 0.f, a2 = 0.f, a3 = 0.f;
        for (int i = threadIdx.x; i < CHUNK; i += 256) {
            float4 xv = x4[i];
            float4 w;
            w = __ldcs(&w4[i]);
            a0 += w.x * xv.x + w.y * xv.y + w.z * xv.z + w.w * xv.w;
            w = __ldcs(&w4[i + NC4]);
            a1 += w.x * xv.x + w.y * xv.y + w.z * xv.z + w.w * xv.w;
            w = __ldcs(&w4[i + 2 * NC4]);
            a2 += w.x * xv.x + w.y * xv.y + w.z * xv.z + w.w * xv.w;
            w = __ldcs(&w4[i + 3 * NC4]);
            a3 += w.x * xv.x + w.y * xv.y + w.z * xv.z + w.w * xv.w;
        }
        s[threadIdx.x] = make_float4(a0, a1, a2, a3);
        __syncthreads();
#pragma unroll
        for (int st = 128; st > 0; st >>= 1) {
            if (threadIdx.x < st) {
                s[threadIdx.x].x += s[threadIdx.x + st].x;
                s[threadIdx.x].y += s[threadIdx.x + st].y;
                s[threadIdx.x].z += s[threadIdx.x + st].z;
                s[threadIdx.x].w += s[threadIdx.x + st].w;
            }
            __syncthreads();
        }
        if (threadIdx.x == 0) {
            float4 r = s[0];
            atomicAdd(&g_f3[r0 + 0], r.x);
            atomicAdd(&g_f3[r0 + 1], r.y);
            atomicAdd(&g_f3[r0 + 2], r.z);
            atomicAdd(&g_f3[r0 + 3], r.w);
        }
        __syncthreads();
    }
}

// ---------------- conv: OCB output channels per thread ----------------------
// grid = (CO/OCB, ceil(OH*OW/TB)), TB=128. Weights for the group in shared.
template <int CI, int KH, int KW, int OCB>
__device__ __forceinline__ void conv_impl(const float* __restrict__ in,
                                          const float* __restrict__ w,
                                          const float* __restrict__ b,
                                          float* __restrict__ out,
                                          int H, int W, int OH, int OW) {
    __shared__ float sw[OCB * CI * KH * KW];
    int oc0 = blockIdx.x * OCB;
    for (int i = threadIdx.x; i < OCB * CI * KH * KW; i += blockDim.x)
        sw[i] = w[oc0 * CI * KH * KW + i];
    __syncthreads();

    int p = blockIdx.y * blockDim.x + threadIdx.x;
    if (p >= OH * OW) return;
    int oy = p / OW, ox = p % OW;
    float acc[OCB];
#pragma unroll
    for (int o = 0; o < OCB; o++) acc[o] = b[oc0 + o];

    for (int ic = 0; ic < CI; ic++) {
        const float* ip = in + ((size_t)ic * H + oy) * W + ox;
        const float* wp = sw + ic * KH * KW;
#pragma unroll
        for (int i = 0; i < KH; i++) {
#pragma unroll
            for (int j = 0; j < KW; j++) {
                float v = ip[i * W + j];
#pragma unroll
                for (int o = 0; o < OCB; o++)
                    acc[o] += wp[o * CI * KH * KW + i * KW + j] * v;
            }
        }
    }
#pragma unroll
    for (int o = 0; o < OCB; o++)
        out[((size_t)(oc0 + o) * OH + oy) * OW + ox] = acc[o];
}

__global__ void k_conv1(const float* __restrict__ w, const float* __restrict__ b) {
    conv_impl<1, 7, 7, 8>(g_v2, w, b, g_c1, 64, 64, 58, 58);
}
__global__ void k_conv2(const float* __restrict__ w, const float* __restrict__ b) {
    conv_impl<32, 5, 5, 4>(g_c1, w, b, g_c2, 58, 58, 54, 54);
}
__global__ void k_conv3(const float* __restrict__ w, const float* __restrict__ b) {
    conv_impl<32, 3, 3, 4>(g_c2, w, b, g_c3, 54, 54, 52, 52);
}
__global__ void k_conv4(const float* __restrict__ w, const float* __restrict__ b) {
    conv_impl<64, 3, 3, 4>(g_c3, w, b, g_c4, 52, 52, 50, 50);
}

// ---------------- launcher --------------------------------------------------
extern "C" void kernel_launch(void* const* d_in, const int* in_sizes, int n_in,
                              void* d_out, int out_size) {
    const float* x     = (const float*)d_in[0];
    const void*  ei    = d_in[1];
    const float* W1    = (const float*)d_in[2];
    const float* b1    = (const float*)d_in[3];
    const float* W2    = (const float*)d_in[4];
    const float* b2    = (const float*)d_in[5];
    const float* fc1_w = (const float*)d_in[6];
    const float* fc1_b = (const float*)d_in[7];
    const float* fc2_w = (const float*)d_in[8];
    const float* fc2_b = (const float*)d_in[9];
    const float* c1_w  = (const float*)d_in[10];
    const float* c1_b  = (const float*)d_in[11];
    const float* c2_w  = (const float*)d_in[12];
    const float* c2_b  = (const float*)d_in[13];
    const float* c3_w  = (const float*)d_in[14];
    const float* c3_b  = (const float*)d_in[15];
    const float* c4_w  = (const float*)d_in[16];
    const float* c4_b  = (const float*)d_in[17];
    const float* fc3_w = (const float*)d_in[18];
    const float* fc3_b = (const float*)d_in[19];
    const float* fc4_w = (const float*)d_in[20];
    const float* fc4_b = (const float*)d_in[21];
    const float* fc5_w = (const float*)d_in[22];
    const float* fc5_b = (const float*)d_in[23];
    float* out = (float*)d_out;

    const int TB = 256;
    const int NB_N = (NN + TB - 1) / TB;
    const int NB_E = (EE + TB - 1) / TB;

    k_detect<<<1, 1024>>>((const unsigned int*)ei);
    k_init<<<8, TB>>>(fc3_b);            // deg zero + f3 bias seed
    k_deg_count<<<NB_E, TB>>>(ei);

    // GCN layer 1
    k_node1<<<NB_N, TB>>>(x, W1);
    k_scatter<<<NB_E, TB>>>(ei);
    // GCN layer 2 (fused boundary)
    k_node2<<<NB_N, TB>>>(b1, W2);
    k_scatter<<<NB_E, TB>>>(ei);
    k_final2<<<NB_N, TB>>>(b2);

    // fc1 [2048,4185], fc2 [4096,2048] — warp per row, 8 rows/block
    k_fc1<<<2048 / 8, TB>>>(fc1_w, fc1_b);
    k_fc2<<<4096 / 8, TB>>>(fc2_w, fc2_b);

    // conv chain (TB=128)
    {
        dim3 g1(32 / 8, (58 * 58 + 127) / 128);
        k_conv1<<<g1, 128>>>(c1_w, c1_b);
        dim3 g2(32 / 4, (54 * 54 + 127) / 128);
        k_conv2<<<g2, 128>>>(c2_w, c2_b);
        dim3 g3(64 / 4, (52 * 52 + 127) / 128);
        k_conv3<<<g3, 128>>>(c3_w, c3_b);
        dim3 g4(64 / 4, (50 * 50 + 127) / 128);
        k_conv4<<<g4, 128>>>(c4_w, c4_b);
    }

    // fc3 [2048,160000] persistent chunked (output pre-seeded with bias)
    k_fc3<<<592, 256>>>(fc3_w);
    // fc4 [2048,2048], fc5 [48,2048]
    k_fc4<<<2048 / 8, TB>>>(fc4_w, fc4_b);
    k_fc5<<<6, TB>>>(fc5_w, fc5_b, out);
}